// round 3
// baseline (speedup 1.0000x reference)
#include <cuda_runtime.h>
#include <math.h>

// Problem constants
#define BATCH 32
#define CIN   3
#define HIN   64
#define WIN   64
#define OCH   256
#define KH    5
#define KW    5
#define HO    60
#define WO    60
#define NPIX  (BATCH*HO*WO)        // 115200
#define DDIM  75                   // CIN*KH*KW
#define YOUT_ELEMS (NPIX*OCH)      // 29491200
#define W_ELEMS (OCH*DDIM)         // 19200

// Scratch (device globals -- allocation-free rule)
__device__ float g_s[(size_t)NPIX * OCH];   // y then r, in [n][o] layout (in-place)
__device__ float g_rx[OCH * 80];            // padded D->80
__device__ float g_rr[OCH * OCH];

// ---------------------------------------------------------------------------
// Kernel 0: zero accumulators
// ---------------------------------------------------------------------------
__global__ void zero_acc_kernel() {
    int idx = blockIdx.x * blockDim.x + threadIdx.x;   // 84*1024 = 86016
    if (idx < OCH * 80) g_rx[idx] = 0.f;
    int j = idx - OCH * 80;
    if (j >= 0 && j < OCH * OCH) g_rr[j] = 0.f;
}

// ---------------------------------------------------------------------------
// Kernel 1: forward conv (implicit GEMM).
// Block = 64 pixels x 256 channels, 256 threads, 8x8 micro-tile.
// K loop = 3 chunks of 25 (one input channel each).
// Writes relu(s) to d_out ([b,o,ho,wo]) AND to g_s ([n][o]).
// ---------------------------------------------------------------------------
__global__ __launch_bounds__(256) void conv_fwd_kernel(
    const float* __restrict__ x, const float* __restrict__ w,
    float* __restrict__ yout)
{
    __shared__ float As[25][64];    // [k][pixel]
    __shared__ float Bs[25][256];   // [k][och]

    const int t  = threadIdx.x;
    const int n0 = blockIdx.x * 64;
    const int to = t >> 3;          // 0..31 channel group
    const int tm = t & 7;           // 0..7 pixel group
    const int ob = to * 8;
    const int mb = tm * 8;

    float acc[8][8];
#pragma unroll
    for (int a = 0; a < 8; ++a)
#pragma unroll
        for (int b = 0; b < 8; ++b) acc[a][b] = 0.f;

    for (int c = 0; c < CIN; ++c) {
        // load x patch tile (im2col on the fly): 25 x 64
        for (int idx = t; idx < 25 * 64; idx += 256) {
            int k = idx >> 6, m = idx & 63;
            int n = n0 + m;
            int b = n / 3600;
            int p = n - b * 3600;
            int ho = p / 60, wo = p - (p / 60) * 60;
            int i = k / 5, j = k - (k / 5) * 5;
            As[k][m] = x[((b * CIN + c) * HIN + ho + i) * WIN + wo + j];
        }
        // load weight tile: 25 x 256
        for (int idx = t; idx < 25 * 256; idx += 256) {
            int k = idx >> 8, o = idx & 255;
            Bs[k][o] = w[(o * CIN + c) * 25 + k];
        }
        __syncthreads();

#pragma unroll
        for (int k = 0; k < 25; ++k) {
            float av[8], bv[8];
            *(float4*)&av[0] = *(const float4*)&As[k][mb];
            *(float4*)&av[4] = *(const float4*)&As[k][mb + 4];
            *(float4*)&bv[0] = *(const float4*)&Bs[k][ob];
            *(float4*)&bv[4] = *(const float4*)&Bs[k][ob + 4];
#pragma unroll
            for (int oo = 0; oo < 8; ++oo)
#pragma unroll
                for (int mm = 0; mm < 8; ++mm)
                    acc[oo][mm] = fmaf(bv[oo], av[mm], acc[oo][mm]);
        }
        __syncthreads();
    }

    // epilogue: relu, write to both layouts
#pragma unroll
    for (int mm = 0; mm < 8; ++mm) {
        int n = n0 + mb + mm;
        int b = n / 3600;
        int p = n - b * 3600;
        float* yo = yout + (size_t)b * (OCH * 3600) + p;
        float* sn = g_s + (size_t)n * OCH + ob;
#pragma unroll
        for (int oo = 0; oo < 8; ++oo) {
            float v = fmaxf(acc[oo][mm], 0.f);
            yo[(ob + oo) * 3600] = v;
            sn[oo] = v;
        }
    }
}

// ---------------------------------------------------------------------------
// Kernel 2: per-pixel winner-take-all + lateral feedback, r = clip(lfb,1)*y
// One block per pixel, 256 threads = 256 channels. In-place on g_s.
// ---------------------------------------------------------------------------
__global__ __launch_bounds__(256) void winner_r_kernel() {
    const int n = blockIdx.x;
    const int o = threadIdx.x;
    float y = g_s[(size_t)n * OCH + o];

    __shared__ float smax[8];
    __shared__ int   wcnt;
    __shared__ int   wlist[256];

    float m = y;
#pragma unroll
    for (int d = 16; d; d >>= 1) m = fmaxf(m, __shfl_xor_sync(0xffffffffu, m, d));
    if ((o & 31) == 0) smax[o >> 5] = m;
    if (o == 0) wcnt = 0;
    __syncthreads();
    if (o == 0) {
        float M = smax[0];
#pragma unroll
        for (int i = 1; i < 8; ++i) M = fmaxf(M, smax[i]);
        smax[0] = M;
    }
    __syncthreads();
    const float M = smax[0];

    if (M > 0.f && y == M) {
        int idx = atomicAdd(&wcnt, 1);
        wlist[idx] = o;
    }
    __syncthreads();

    float r = 0.f;
    if (M > 0.f) {
        const int i = o >> 4, j = o & 15;
        float lfb = 0.f;
        const int cnt = wcnt;
        for (int q = 0; q < cnt; ++q) {
            int wi = wlist[q];
            int di = (wi >> 4) - i;
            int dj = (wi & 15) - j;
            if (di >= -7 && di <= 8 && dj >= -7 && dj <= 8) {
                int adi = di < 0 ? -di : di;
                int adj = dj < 0 ? -dj : dj;
                int ch = adi > adj ? adi : adj;
                lfb += expf(-(float)(ch * ch) * (1.f / 98.f));
            }
        }
        lfb = fminf(lfb, 1.f);
        r = lfb * y;
    }
    g_s[(size_t)n * OCH + o] = r;
}

// ---------------------------------------------------------------------------
// Kernel 3: rx = r^T @ x_unf   [256 x 75] (padded to 80), split-K + atomics.
// 320 threads: og(32 groups of 8 o) x dg(10 groups of 8 d). Chunk = 384 pixels.
// ---------------------------------------------------------------------------
#define RX_CHUNK 384
__global__ __launch_bounds__(320) void rx_kernel(const float* __restrict__ x)
{
    __shared__ float Rs[32][256];
    __shared__ float Xs[32][80];

    const int t  = threadIdx.x;
    const int n0 = blockIdx.x * RX_CHUNK;
    const int og = t / 10, dg = t - (t / 10) * 10;
    const int ob = og * 8, db = dg * 8;

    float acc[8][8];
#pragma unroll
    for (int a = 0; a < 8; ++a)
#pragma unroll
        for (int b = 0; b < 8; ++b) acc[a][b] = 0.f;

    for (int s = 0; s < RX_CHUNK; s += 32) {
        const int nb = n0 + s;
        for (int idx = t; idx < 32 * 256; idx += 320) {
            int kn = idx >> 8, o = idx & 255;
            Rs[kn][o] = g_s[(size_t)(nb + kn) * OCH + o];
        }
        for (int idx = t; idx < 32 * 80; idx += 320) {
            int kn = idx / 80, d = idx - (idx / 80) * 80;
            float v = 0.f;
            if (d < DDIM) {
                int n = nb + kn;
                int b = n / 3600;
                int p = n - b * 3600;
                int ho = p / 60, wo = p - (p / 60) * 60;
                int c = d / 25, rem = d - (d / 25) * 25;
                int i = rem / 5, j = rem - (rem / 5) * 5;
                v = x[((b * CIN + c) * HIN + ho + i) * WIN + wo + j];
            }
            Xs[kn][d] = v;
        }
        __syncthreads();
#pragma unroll 8
        for (int kn = 0; kn < 32; ++kn) {
            float rv[8], xv[8];
            *(float4*)&rv[0] = *(const float4*)&Rs[kn][ob];
            *(float4*)&rv[4] = *(const float4*)&Rs[kn][ob + 4];
            *(float4*)&xv[0] = *(const float4*)&Xs[kn][db];
            *(float4*)&xv[4] = *(const float4*)&Xs[kn][db + 4];
#pragma unroll
            for (int oo = 0; oo < 8; ++oo)
#pragma unroll
                for (int dd = 0; dd < 8; ++dd)
                    acc[oo][dd] = fmaf(rv[oo], xv[dd], acc[oo][dd]);
        }
        __syncthreads();
    }

#pragma unroll
    for (int oo = 0; oo < 8; ++oo)
#pragma unroll
        for (int dd = 0; dd < 8; ++dd)
            atomicAdd(&g_rx[(ob + oo) * 80 + db + dd], acc[oo][dd]);
}

// ---------------------------------------------------------------------------
// Kernel 4: rr = r^T @ r, lower-triangle 64x64 tiles only (10 tiles), split-K.
// 256 threads, 4x4 micro-tile. Chunk = 1152 pixels (100 splits).
// ---------------------------------------------------------------------------
#define RR_CHUNK 1152
__global__ __launch_bounds__(256) void rr_kernel()
{
    const int ti_lut[10] = {0,1,1,2,2,2,3,3,3,3};
    const int tj_lut[10] = {0,0,1,0,1,2,0,1,2,3};

    __shared__ float Ri[32][64];
    __shared__ float Rj[32][64];

    const int tile = blockIdx.x % 10;
    const int ks   = blockIdx.x / 10;
    const int ti = ti_lut[tile], tj = tj_lut[tile];
    const int t  = threadIdx.x;
    const int ty = t >> 4, tx = t & 15;
    const int n0 = ks * RR_CHUNK;

    float acc[4][4];
#pragma unroll
    for (int a = 0; a < 4; ++a)
#pragma unroll
        for (int b = 0; b < 4; ++b) acc[a][b] = 0.f;

    for (int s = 0; s < RR_CHUNK; s += 32) {
        const int nb = n0 + s;
        for (int idx = t; idx < 32 * 64; idx += 256) {
            int kn = idx >> 6, oo = idx & 63;
            Ri[kn][oo] = g_s[(size_t)(nb + kn) * OCH + ti * 64 + oo];
            Rj[kn][oo] = g_s[(size_t)(nb + kn) * OCH + tj * 64 + oo];
        }
        __syncthreads();
#pragma unroll 8
        for (int kn = 0; kn < 32; ++kn) {
            float4 a4 = *(const float4*)&Ri[kn][ty * 4];
            float4 b4 = *(const float4*)&Rj[kn][tx * 4];
            float av[4] = {a4.x, a4.y, a4.z, a4.w};
            float bv[4] = {b4.x, b4.y, b4.z, b4.w};
#pragma unroll
            for (int ii = 0; ii < 4; ++ii)
#pragma unroll
                for (int jj = 0; jj < 4; ++jj)
                    acc[ii][jj] = fmaf(av[ii], bv[jj], acc[ii][jj]);
        }
        __syncthreads();
    }

#pragma unroll
    for (int ii = 0; ii < 4; ++ii)
#pragma unroll
        for (int jj = 0; jj < 4; ++jj)
            atomicAdd(&g_rr[(ti * 64 + ty * 4 + ii) * OCH + tj * 64 + tx * 4 + jj],
                      acc[ii][jj]);
}

// ---------------------------------------------------------------------------
// Kernel 5: weight update.  new_w[o,d] = w + eta*(rx - sum_{j<=o} rr[o,j] w[j,d])/N
// ---------------------------------------------------------------------------
__global__ void update_w_kernel(const float* __restrict__ w, float* __restrict__ outw)
{
    const int o = blockIdx.x;
    const int d = threadIdx.x;   // 75 threads
    float acc = 0.f;
    for (int j = 0; j <= o; ++j)
        acc = fmaf(g_rr[o * OCH + j], w[j * DDIM + d], acc);
    float delta = (g_rx[o * 80 + d] - acc) * (1.f / (float)NPIX);
    outw[o * DDIM + d] = w[o * DDIM + d] + 0.01f * delta;
}

// ---------------------------------------------------------------------------
extern "C" void kernel_launch(void* const* d_in, const int* in_sizes, int n_in,
                              void* d_out, int out_size)
{
    const float* x = (const float*)d_in[0];
    const float* w = (const float*)d_in[1];
    float* out  = (float*)d_out;
    float* yout = out;
    float* outw = out + (out_size - W_ELEMS);

    zero_acc_kernel<<<84, 1024>>>();
    conv_fwd_kernel<<<NPIX / 64, 256>>>(x, w, yout);
    winner_r_kernel<<<NPIX, 256>>>();
    rx_kernel<<<NPIX / RX_CHUNK, 320>>>(x);
    rr_kernel<<<(NPIX / RR_CHUNK) * 10, 256>>>();
    update_w_kernel<<<OCH, DDIM>>>(w, outw);
}

// round 4
// speedup vs baseline: 1.2867x; 1.2867x over previous
#include <cuda_runtime.h>
#include <cuda_bf16.h>
#include <mma.h>
#include <math.h>

using namespace nvcuda;

// Problem constants
#define BATCH 32
#define CIN   3
#define HIN   64
#define WIN   64
#define OCH   256
#define KH    5
#define KW    5
#define HO    60
#define WO    60
#define NPIX  (BATCH*HO*WO)        // 115200
#define DDIM  75
#define W_ELEMS (OCH*DDIM)         // 19200

#define RR_NSPLIT 200
#define RR_CHUNK  576              // 115200/200
#define RX_NSPLIT 300
#define RX_CHUNK  384              // 115200/300
#define DPAD 96                    // D padded to 96 for wmma

// Scratch (device globals -- allocation-free rule)
__device__ unsigned short g_rbf[(size_t)NPIX * OCH];    // r in bf16, [n][o]
__device__ unsigned short g_xbf[(size_t)NPIX * DPAD];   // x_unf in bf16, [n][96]
__device__ float g_rr_part[(size_t)3 * RR_NSPLIT * 128 * 128];
__device__ float g_rx_part[(size_t)2 * RX_NSPLIT * 128 * DPAD];
__device__ float g_rr[OCH * OCH];
__device__ float g_rx[OCH * DPAD];

// ---------------------------------------------------------------------------
// Kernel A: x_unf -> bf16, padded to 96 cols
// ---------------------------------------------------------------------------
__global__ void xunf_bf16_kernel(const float* __restrict__ x) {
    int idx = blockIdx.x * blockDim.x + threadIdx.x;
    if (idx >= NPIX * DPAD) return;
    int n = idx / DPAD, d = idx - n * DPAD;
    float v = 0.f;
    if (d < DDIM) {
        int b = n / 3600, p = n - b * 3600;
        int ho = p / 60, wo = p - (p / 60) * 60;
        int c = d / 25, rem = d - c * 25;
        int i = rem / 5, j = rem - (rem / 5) * 5;
        v = x[((b * CIN + c) * HIN + ho + i) * WIN + wo + j];
    }
    ((__nv_bfloat16*)g_xbf)[idx] = __float2bfloat16(v);
}

// ---------------------------------------------------------------------------
// Kernel B: forward conv (implicit GEMM, fp32) fused with WTA + LFB.
// Block = 64 pixels x 256 channels, 256 threads, 8x8 micro-tile.
// Writes relu(s) to yout (fp32) and r to g_rbf (bf16).
// ---------------------------------------------------------------------------
__global__ __launch_bounds__(256) void conv_fused_kernel(
    const float* __restrict__ x, const float* __restrict__ w,
    float* __restrict__ yout)
{
    __shared__ float As[25][64];
    __shared__ float Bs[25][256];
    __shared__ float pmax[64];
    __shared__ unsigned wmask[64][8];

    const int t  = threadIdx.x;
    const int n0 = blockIdx.x * 64;
    const int to = t >> 3;
    const int tm = t & 7;
    const int ob = to * 8;
    const int mb = tm * 8;

    if (t < 64) pmax[t] = 0.f;
    for (int idx = t; idx < 512; idx += 256) ((unsigned*)wmask)[idx] = 0u;

    float acc[8][8];
#pragma unroll
    for (int a = 0; a < 8; ++a)
#pragma unroll
        for (int b = 0; b < 8; ++b) acc[a][b] = 0.f;

    for (int c = 0; c < CIN; ++c) {
        for (int idx = t; idx < 25 * 64; idx += 256) {
            int k = idx >> 6, m = idx & 63;
            int n = n0 + m;
            int b = n / 3600;
            int p = n - b * 3600;
            int ho = p / 60, wo = p - (p / 60) * 60;
            int i = k / 5, j = k - (k / 5) * 5;
            As[k][m] = x[((b * CIN + c) * HIN + ho + i) * WIN + wo + j];
        }
        for (int idx = t; idx < 25 * 256; idx += 256) {
            int k = idx >> 8, o = idx & 255;
            Bs[k][o] = w[(o * CIN + c) * 25 + k];
        }
        __syncthreads();

#pragma unroll
        for (int k = 0; k < 25; ++k) {
            float av[8], bv[8];
            *(float4*)&av[0] = *(const float4*)&As[k][mb];
            *(float4*)&av[4] = *(const float4*)&As[k][mb + 4];
            *(float4*)&bv[0] = *(const float4*)&Bs[k][ob];
            *(float4*)&bv[4] = *(const float4*)&Bs[k][ob + 4];
#pragma unroll
            for (int oo = 0; oo < 8; ++oo)
#pragma unroll
                for (int mm = 0; mm < 8; ++mm)
                    acc[oo][mm] = fmaf(bv[oo], av[mm], acc[oo][mm]);
        }
        __syncthreads();
    }

    // relu in place
#pragma unroll
    for (int oo = 0; oo < 8; ++oo)
#pragma unroll
        for (int mm = 0; mm < 8; ++mm)
            acc[oo][mm] = fmaxf(acc[oo][mm], 0.f);

    // per-pixel max (nonneg floats compare correctly as ints)
#pragma unroll
    for (int mm = 0; mm < 8; ++mm) {
        float tmx = acc[0][mm];
#pragma unroll
        for (int oo = 1; oo < 8; ++oo) tmx = fmaxf(tmx, acc[oo][mm]);
        atomicMax((int*)&pmax[mb + mm], __float_as_int(tmx));
    }
    __syncthreads();

    // winner bitmask
#pragma unroll
    for (int mm = 0; mm < 8; ++mm) {
        float M = pmax[mb + mm];
        if (M > 0.f) {
#pragma unroll
            for (int oo = 0; oo < 8; ++oo)
                if (acc[oo][mm] == M)
                    atomicOr(&wmask[mb + mm][(ob + oo) >> 5], 1u << ((ob + oo) & 31));
        }
    }
    __syncthreads();

    // write y_out (fp32) and r (bf16)
    __nv_bfloat16* rbf = (__nv_bfloat16*)g_rbf;
#pragma unroll
    for (int mm = 0; mm < 8; ++mm) {
        int n = n0 + mb + mm;
        int b = n / 3600, p = n - b * 3600;
        float* yo = yout + (size_t)b * (OCH * 3600) + p;
        __nv_bfloat16* rn = rbf + (size_t)n * OCH + ob;
        float M = pmax[mb + mm];
        const unsigned* msk = wmask[mb + mm];
#pragma unroll
        for (int oo = 0; oo < 8; ++oo) {
            float v = acc[oo][mm];
            yo[(ob + oo) * 3600] = v;
            float r = 0.f;
            if (v > 0.f && M > 0.f) {
                int ch = ob + oo;
                int ii = ch >> 4, jj = ch & 15;
                float lfb = 0.f;
                for (int wd = 0; wd < 8; ++wd) {
                    unsigned m_ = msk[wd];
                    while (m_) {
                        int bit = __ffs(m_) - 1; m_ &= m_ - 1;
                        int wi = wd * 32 + bit;
                        int di = (wi >> 4) - ii, dj = (wi & 15) - jj;
                        if (di >= -7 && di <= 8 && dj >= -7 && dj <= 8) {
                            int adi = di < 0 ? -di : di;
                            int adj = dj < 0 ? -dj : dj;
                            int cb = adi > adj ? adi : adj;
                            lfb += expf((float)(cb * cb) * (-1.f / 98.f));
                        }
                    }
                }
                r = fminf(lfb, 1.f) * v;
            }
            rn[oo] = __float2bfloat16(r);
        }
    }
}

// ---------------------------------------------------------------------------
// Kernel C: rr = r^T r via bf16 WMMA. Lower triangle as 3 tiles of 128x128:
// (ti,tj) = (0,0),(1,0),(1,1). Split-K into RR_NSPLIT partials.
// Block 256 thr (8 warps, 4x2), warp tile 32x64 (2x4 fragments).
// ---------------------------------------------------------------------------
__global__ __launch_bounds__(256) void rr_wmma_kernel() {
    const int tile  = blockIdx.x % 3;
    const int split = blockIdx.x / 3;
    const int ti = (tile == 0) ? 0 : 1;
    const int tj = (tile == 2) ? 1 : 0;
    const int warp = threadIdx.x >> 5;
    const int wr = warp & 3;
    const int wc = warp >> 2;

    __shared__ __nv_bfloat16 Ri[32][136];
    __shared__ __nv_bfloat16 Rj[32][136];

    wmma::fragment<wmma::accumulator, 16, 16, 16, float> c[2][4];
#pragma unroll
    for (int i = 0; i < 2; ++i)
#pragma unroll
        for (int j = 0; j < 4; ++j) wmma::fill_fragment(c[i][j], 0.f);

    const __nv_bfloat16* rbf = (const __nv_bfloat16*)g_rbf;
    const int n0 = split * RR_CHUNK;

    for (int s = 0; s < RR_CHUNK; s += 32) {
        for (int idx = threadIdx.x; idx < 512; idx += 256) {
            int kn = idx >> 4;
            int c8 = (idx & 15) << 3;
            size_t base = (size_t)(n0 + s + kn) * OCH;
            *(uint4*)&Ri[kn][c8] = *(const uint4*)&rbf[base + ti * 128 + c8];
            *(uint4*)&Rj[kn][c8] = *(const uint4*)&rbf[base + tj * 128 + c8];
        }
        __syncthreads();
#pragma unroll
        for (int kk = 0; kk < 32; kk += 16) {
            wmma::fragment<wmma::matrix_a, 16, 16, 16, __nv_bfloat16, wmma::col_major> a[2];
            wmma::fragment<wmma::matrix_b, 16, 16, 16, __nv_bfloat16, wmma::row_major> b[4];
#pragma unroll
            for (int i = 0; i < 2; ++i)
                wmma::load_matrix_sync(a[i], &Ri[kk][wr * 32 + i * 16], 136);
#pragma unroll
            for (int j = 0; j < 4; ++j)
                wmma::load_matrix_sync(b[j], &Rj[kk][wc * 64 + j * 16], 136);
#pragma unroll
            for (int i = 0; i < 2; ++i)
#pragma unroll
                for (int j = 0; j < 4; ++j)
                    wmma::mma_sync(c[i][j], a[i], b[j], c[i][j]);
        }
        __syncthreads();
    }

    float* outp = g_rr_part + ((size_t)tile * RR_NSPLIT + split) * 16384;
#pragma unroll
    for (int i = 0; i < 2; ++i)
#pragma unroll
        for (int j = 0; j < 4; ++j)
            wmma::store_matrix_sync(&outp[(wr * 32 + i * 16) * 128 + wc * 64 + j * 16],
                                    c[i][j], 128, wmma::mem_row_major);
}

// ---------------------------------------------------------------------------
// Kernel D: rx = r^T x_unf via bf16 WMMA. Output 256x96, block tile 128x96,
// grid = 2 o-halves x RX_NSPLIT. Warp tile 32x48 (2x3 fragments).
// ---------------------------------------------------------------------------
__global__ __launch_bounds__(256) void rx_wmma_kernel() {
    const int oh    = blockIdx.x & 1;
    const int split = blockIdx.x >> 1;
    const int warp = threadIdx.x >> 5;
    const int wr = warp & 3;
    const int wc = warp >> 2;

    __shared__ __nv_bfloat16 Ra[32][136];
    __shared__ __nv_bfloat16 Xs[32][DPAD];

    wmma::fragment<wmma::accumulator, 16, 16, 16, float> c[2][3];
#pragma unroll
    for (int i = 0; i < 2; ++i)
#pragma unroll
        for (int j = 0; j < 3; ++j) wmma::fill_fragment(c[i][j], 0.f);

    const __nv_bfloat16* rbf = (const __nv_bfloat16*)g_rbf;
    const __nv_bfloat16* xbf = (const __nv_bfloat16*)g_xbf;
    const int n0 = split * RX_CHUNK;

    for (int s = 0; s < RX_CHUNK; s += 32) {
        for (int idx = threadIdx.x; idx < 512; idx += 256) {
            int kn = idx >> 4;
            int c8 = (idx & 15) << 3;
            *(uint4*)&Ra[kn][c8] =
                *(const uint4*)&rbf[(size_t)(n0 + s + kn) * OCH + oh * 128 + c8];
        }
        for (int idx = threadIdx.x; idx < 384; idx += 256) {
            int kn = idx / 12;
            int c8 = (idx % 12) << 3;
            *(uint4*)&Xs[kn][c8] = *(const uint4*)&xbf[(size_t)(n0 + s + kn) * DPAD + c8];
        }
        __syncthreads();
#pragma unroll
        for (int kk = 0; kk < 32; kk += 16) {
            wmma::fragment<wmma::matrix_a, 16, 16, 16, __nv_bfloat16, wmma::col_major> a[2];
            wmma::fragment<wmma::matrix_b, 16, 16, 16, __nv_bfloat16, wmma::row_major> b[3];
#pragma unroll
            for (int i = 0; i < 2; ++i)
                wmma::load_matrix_sync(a[i], &Ra[kk][wr * 32 + i * 16], 136);
#pragma unroll
            for (int j = 0; j < 3; ++j)
                wmma::load_matrix_sync(b[j], &Xs[kk][wc * 48 + j * 16], DPAD);
#pragma unroll
            for (int i = 0; i < 2; ++i)
#pragma unroll
                for (int j = 0; j < 3; ++j)
                    wmma::mma_sync(c[i][j], a[i], b[j], c[i][j]);
        }
        __syncthreads();
    }

    float* outp = g_rx_part + ((size_t)oh * RX_NSPLIT + split) * (128 * DPAD);
#pragma unroll
    for (int i = 0; i < 2; ++i)
#pragma unroll
        for (int j = 0; j < 3; ++j)
            wmma::store_matrix_sync(&outp[(wr * 32 + i * 16) * DPAD + wc * 48 + j * 16],
                                    c[i][j], DPAD, wmma::mem_row_major);
}

// ---------------------------------------------------------------------------
// Kernel E/F: reduce partials
// ---------------------------------------------------------------------------
__global__ void reduce_rr_kernel() {
    int idx = blockIdx.x * blockDim.x + threadIdx.x;   // 0..49151
    int tile = idx / 16384, ij = idx - tile * 16384;
    int i = ij >> 7, j = ij & 127;
    const float* p = g_rr_part + (size_t)tile * RR_NSPLIT * 16384 + ij;
    float s = 0.f;
    for (int k = 0; k < RR_NSPLIT; ++k) s += p[(size_t)k * 16384];
    int ti = (tile == 0) ? 0 : 1;
    int tj = (tile == 2) ? 1 : 0;
    g_rr[(ti * 128 + i) * OCH + tj * 128 + j] = s;
}

__global__ void reduce_rx_kernel() {
    int idx = blockIdx.x * blockDim.x + threadIdx.x;   // 0..24575
    int oh = idx / (128 * DPAD), ij = idx - oh * (128 * DPAD);
    const float* p = g_rx_part + (size_t)oh * RX_NSPLIT * (128 * DPAD) + ij;
    float s = 0.f;
    for (int k = 0; k < RX_NSPLIT; ++k) s += p[(size_t)k * (128 * DPAD)];
    g_rx[oh * (128 * DPAD) + ij] = s;
}

// ---------------------------------------------------------------------------
// Kernel G: weight update
// ---------------------------------------------------------------------------
__global__ void update_w_kernel(const float* __restrict__ w, float* __restrict__ outw)
{
    const int o = blockIdx.x;
    const int d = threadIdx.x;   // 75 threads
    float acc = 0.f;
    for (int j = 0; j <= o; ++j)
        acc = fmaf(g_rr[o * OCH + j], w[j * DDIM + d], acc);
    float delta = (g_rx[o * DPAD + d] - acc) * (1.f / (float)NPIX);
    outw[o * DDIM + d] = w[o * DDIM + d] + 0.01f * delta;
}

// ---------------------------------------------------------------------------
extern "C" void kernel_launch(void* const* d_in, const int* in_sizes, int n_in,
                              void* d_out, int out_size)
{
    const float* x = (const float*)d_in[0];
    const float* w = (const float*)d_in[1];
    float* out  = (float*)d_out;
    float* yout = out;
    float* outw = out + (out_size - W_ELEMS);

    xunf_bf16_kernel<<<(NPIX * DPAD + 255) / 256, 256>>>(x);
    conv_fused_kernel<<<NPIX / 64, 256>>>(x, w, yout);
    rr_wmma_kernel<<<3 * RR_NSPLIT, 256>>>();
    rx_wmma_kernel<<<2 * RX_NSPLIT, 256>>>();
    reduce_rr_kernel<<<192, 256>>>();
    reduce_rx_kernel<<<96, 256>>>();
    update_w_kernel<<<OCH, DDIM>>>(w, outw);
}